// round 15
// baseline (speedup 1.0000x reference)
#include <cuda_runtime.h>
#include <cuda_fp16.h>
#include <cstdint>

// ---------------- problem constants ----------------
#define EDGE_DIM 32
#define MID      64
#define NCIN     32
#define NCOUT    32
#define MO       3
#define QDIM     96
#define RADW     3072
#define EMAX     32768
#define NCHUNK   32
#define HP       68            // h smem pitch (floats)

// scratch: per chunk 12288 B fragment-register-order fp16 W3 image, n-thirds
__device__ __half g_B[NCHUNK * 12288 / 2];

// ---------------- helpers ----------------
__device__ __forceinline__ float gelu_exact(float x) {
    return 0.5f * x * (1.0f + erff(x * 0.70710678118654752440f));
}
__device__ __forceinline__ float warp_allreduce_sum(float v) {
    v += __shfl_xor_sync(0xffffffffu, v, 16);
    v += __shfl_xor_sync(0xffffffffu, v, 8);
    v += __shfl_xor_sync(0xffffffffu, v, 4);
    v += __shfl_xor_sync(0xffffffffu, v, 2);
    v += __shfl_xor_sync(0xffffffffu, v, 1);
    return v;
}
__device__ __forceinline__ uint32_t pack_h2(float x, float y) {
    half2 h = __floats2half2_rn(x, y);
    return *(uint32_t*)&h;
}
__device__ __forceinline__ void mma16816(float c[4], const uint32_t a[4],
                                         uint32_t b0, uint32_t b1) {
    asm volatile(
        "mma.sync.aligned.m16n8k16.row.col.f32.f16.f16.f32 "
        "{%0,%1,%2,%3}, {%4,%5,%6,%7}, {%8,%9}, {%0,%1,%2,%3};"
        : "+f"(c[0]), "+f"(c[1]), "+f"(c[2]), "+f"(c[3])
        : "r"(a[0]), "r"(a[1]), "r"(a[2]), "r"(a[3]), "r"(b0), "r"(b1));
}
__device__ __forceinline__ void cp_async16(uint32_t smem_dst, const void* gsrc) {
    asm volatile("cp.async.cg.shared.global [%0], [%1], 16;"
                 :: "r"(smem_dst), "l"(gsrc) : "memory");
}

// ---------------- Kernel P: W3 -> fp16 fragment image, n in thirds of 32 ----
__global__ void __launch_bounds__(256) prep_w3(const float* __restrict__ W3) {
    int idx = blockIdx.x * 256 + threadIdx.x;     // over 64*3072
    if (idx >= MID * RADW) return;
    int k = idx / RADW, n = idx % RADW;
    int chunk = n / QDIM, nl = n % QDIM;
    int ng = nl / 32, nq = nl % 32;               // third, pos within third
    int nt = nq >> 3, rr = nq & 7;                // nt in 0..3
    int kt = k >> 4, kk = k & 15;
    int cc = (kk >> 1) & 3, bb = kk >> 3, hp = kk & 1;
    int lane = rr * 4 + cc;
    int j = kt * 2 + (nt >> 1);                   // 8 j-positions per third
    int r4 = ((nt & 1) << 1) + bb;
    int off = chunk * 12288 + ng * 4096 + j * 512 + lane * 16 + r4 * 4 + hp * 2;
    g_B[off >> 1] = __float2half_rn(W3[idx]);
}

// ---------------- Kernel M: fused MLP + mma.sync, 768 thr / 24 warps ----------------
// warp = 16 edges x 32 n; 8 edge-groups x 3 n-thirds; 128 edges per CTA.
#define SM_B     0                          // 2 x 12288 = 24576
#define SM_T     24576                      // 128 x 832 = 106496 -> 131072
#define SM_PED   131072                     // 2 parity x 768 floats = 6144 -> 137216
#define SM_W     137216                     // 6528 floats = 26112 -> 163328
#define SM_H     163328                     // 128 x 68 x 4 = 34816 -> 198144
#define SM_TOTAL 198144

__global__ void __launch_bounds__(768, 1) pair_main_kernel(
    const float* __restrict__ edges,
    const float* __restrict__ feats,
    const float* __restrict__ basis,
    const float* __restrict__ W1, const float* __restrict__ b1,
    const float* __restrict__ g1, const float* __restrict__ be1,
    const float* __restrict__ W2, const float* __restrict__ b2,
    const float* __restrict__ g2, const float* __restrict__ be2,
    float* __restrict__ out,
    int E)
{
    extern __shared__ __align__(1024) char smem[];
    const uint32_t smem_u32 = (uint32_t)__cvta_generic_to_shared(smem);
    const int tid = threadIdx.x, w = tid >> 5, lane = tid & 31;
    const int r = lane >> 2, c = lane & 3;
    const int eg = w / 3, ng = w % 3;         // eg 0..7, ng 0..2
    const int E0 = blockIdx.x * 128;
    const int ebase = eg * 16 + r;

    float* hsm = (float*)(smem + SM_H);
    float* Wsm = (float*)(smem + SM_W);
    float* W1s = Wsm;               // 2048
    float* W2s = Wsm + 2048;        // 4096
    float* prm = Wsm + 6144;        // 384

    const float4* gB4 = (const float4*)g_B;

    // ---- stage chunks 0,1 via cp.async (1536 lines, 2 per thread) ----
    {
        cp_async16(smem_u32 + SM_B + tid * 16, gB4 + tid);
        cp_async16(smem_u32 + SM_B + (tid + 768) * 16, gB4 + tid + 768);
        asm volatile("cp.async.commit_group;" ::: "memory");
    }

    // ---- load MLP weights ----
    for (int i = tid; i < EDGE_DIM * MID; i += 768) W1s[i] = W1[i];
    for (int i = tid; i < MID * MID; i += 768)      W2s[i] = W2[i];
    if (tid < MID) {
        prm[tid] = b1[tid]; prm[MID + tid] = g1[tid]; prm[2*MID + tid] = be1[tid];
        prm[3*MID + tid] = b2[tid]; prm[4*MID + tid] = g2[tid]; prm[5*MID + tid] = be2[tid];
    }

    // ---- T tile: [e][qp] pitch 832; one uint4 = fp16 {t0, t1} ----
    for (int idx = tid; idx < 128 * 48; idx += 768) {
        const int e = idx / 48, qp = idx - e * 48;
        const int q0 = 2 * qp, q1 = q0 + 1;
        const int i0 = q0 / 3, f0 = q0 % 3, i1 = q1 / 3, f1 = q1 % 3;
        const float* fe = feats + (size_t)(E0 + e) * (NCIN * 3);
        const float* be = basis + (size_t)(E0 + e) * 27;
        const float a0 = fe[i0*3], a1 = fe[i0*3+1], a2 = fe[i0*3+2];
        const float b0 = fe[i1*3], b1v = fe[i1*3+1], b2v = fe[i1*3+2];
        float t0[3], t1[3];
        #pragma unroll
        for (int m = 0; m < 3; m++) {
            t0[m] = a0 * be[f0*3+m] + a1  * be[9 + f0*3+m] + a2  * be[18 + f0*3+m];
            t1[m] = b0 * be[f1*3+m] + b1v * be[9 + f1*3+m] + b2v * be[18 + f1*3+m];
        }
        uint4 v;
        v.x = pack_h2(t0[0], t0[1]);
        v.y = pack_h2(t0[2], 0.0f);
        v.z = pack_h2(t1[0], t1[1]);
        v.w = pack_h2(t1[2], 0.0f);
        *(uint4*)(smem + SM_T + e * 832 + qp * 16) = v;
    }
    __syncthreads();    // weights + T visible

    // ---- fused MLP: warp w computes edges {w, w+24, w+48, ...} ----
    for (int el = w; el < 128; el += 24) {
        const float xv = edges[(size_t)(E0 + el) * EDGE_DIM + lane];
        float a0 = prm[lane], a1 = prm[lane + 32];
        #pragma unroll
        for (int k = 0; k < 32; k++) {
            const float xk = __shfl_sync(0xffffffffu, xv, k);
            a0 = fmaf(xk, W1s[k * MID + lane], a0);
            a1 = fmaf(xk, W1s[k * MID + lane + 32], a1);
        }
        float mean = warp_allreduce_sum(a0 + a1) * (1.0f / 64.0f);
        float d0 = a0 - mean, d1 = a1 - mean;
        float var = warp_allreduce_sum(d0 * d0 + d1 * d1) * (1.0f / 64.0f);
        float inv = rsqrtf(var + 1e-5f);
        a0 = gelu_exact(d0 * inv * prm[MID + lane]      + prm[2*MID + lane]);
        a1 = gelu_exact(d1 * inv * prm[MID + lane + 32] + prm[2*MID + lane + 32]);
        float c0 = prm[3*MID + lane], c1 = prm[3*MID + lane + 32];
        #pragma unroll
        for (int k = 0; k < 32; k++) {
            const float u  = __shfl_sync(0xffffffffu, a0, k);
            const float v2 = __shfl_sync(0xffffffffu, a1, k);
            c0 = fmaf(u,  W2s[k * MID + lane], c0);
            c0 = fmaf(v2, W2s[(k + 32) * MID + lane], c0);
            c1 = fmaf(u,  W2s[k * MID + lane + 32], c1);
            c1 = fmaf(v2, W2s[(k + 32) * MID + lane + 32], c1);
        }
        mean = warp_allreduce_sum(c0 + c1) * (1.0f / 64.0f);
        d0 = c0 - mean; d1 = c1 - mean;
        var = warp_allreduce_sum(d0 * d0 + d1 * d1) * (1.0f / 64.0f);
        inv = rsqrtf(var + 1e-5f);
        c0 = gelu_exact(d0 * inv * prm[4*MID + lane]      + prm[5*MID + lane]);
        c1 = gelu_exact(d1 * inv * prm[4*MID + lane + 32] + prm[5*MID + lane + 32]);
        hsm[el * HP + lane]      = c0;
        hsm[el * HP + lane + 32] = c1;
    }
    asm volatile("cp.async.wait_group 0;" ::: "memory");
    __syncthreads();    // h visible; B chunks 0,1 landed

    // ---- A fragments (16 edges: rows ebase, ebase+8) ----
    uint32_t A[4][4];
    {
        const float* h0 = hsm + ebase * HP;
        const float* h1 = hsm + (ebase + 8) * HP;
        #pragma unroll
        for (int kt = 0; kt < 4; kt++) {
            const int k0 = kt * 16 + 2 * c;
            float2 p0 = *(const float2*)(h0 + k0);
            float2 p1 = *(const float2*)(h0 + k0 + 8);
            float2 p2 = *(const float2*)(h1 + k0);
            float2 p3 = *(const float2*)(h1 + k0 + 8);
            A[kt][0] = pack_h2(p0.x, p0.y);
            A[kt][1] = pack_h2(p2.x, p2.y);
            A[kt][2] = pack_h2(p1.x, p1.y);
            A[kt][3] = pack_h2(p3.x, p3.y);
        }
    }

    float* ped = (float*)(smem + SM_PED);

    for (int o = 0; o < NCHUNK; o++) {
        // stage next chunk via cp.async (768 lines, 1 per thread)
        if (o + 1 < NCHUNK) {
            const uint32_t dst = smem_u32 + SM_B + ((o + 1) & 1) * 12288;
            cp_async16(dst + tid * 16, gB4 + (size_t)(o + 1) * 768 + tid);
            asm volatile("cp.async.commit_group;" ::: "memory");
        }

        const char* buf = smem + SM_B + (o & 1) * 12288 + ng * 4096;
        float C[4][4];
        #pragma unroll
        for (int nt = 0; nt < 4; nt++) {
            C[nt][0] = 0.f; C[nt][1] = 0.f; C[nt][2] = 0.f; C[nt][3] = 0.f;
        }

        #pragma unroll
        for (int kt = 0; kt < 4; kt++) {
            uint4 b0 = *(const uint4*)(buf + (kt * 2) * 512 + lane * 16);
            uint4 b1 = *(const uint4*)(buf + (kt * 2 + 1) * 512 + lane * 16);
            mma16816(C[0], A[kt], b0.x, b0.y);
            mma16816(C[1], A[kt], b0.z, b0.w);
            mma16816(C[2], A[kt], b1.x, b1.y);
            mma16816(C[3], A[kt], b1.z, b1.w);
        }

        // ---- epilogue: both s-slots from smem ----
        float acc[2][3];
        acc[0][0]=0.f; acc[0][1]=0.f; acc[0][2]=0.f;
        acc[1][0]=0.f; acc[1][1]=0.f; acc[1][2]=0.f;

        #pragma unroll
        for (int nt = 0; nt < 4; nt++) {
            const int qp = ng * 16 + nt * 4 + c;
            uint4 tv0 = *(const uint4*)(smem + SM_T + ebase * 832 + qp * 16);
            float2 a0v = __half22float2(*(half2*)&tv0.x);
            float2 a1v = __half22float2(*(half2*)&tv0.y);
            float2 a2v = __half22float2(*(half2*)&tv0.z);
            float2 a3v = __half22float2(*(half2*)&tv0.w);
            const float cA0 = C[nt][0], cB0 = C[nt][1];
            acc[0][0] = fmaf(cA0, a0v.x, fmaf(cB0, a2v.x, acc[0][0]));
            acc[0][1] = fmaf(cA0, a0v.y, fmaf(cB0, a2v.y, acc[0][1]));
            acc[0][2] = fmaf(cA0, a1v.x, fmaf(cB0, a3v.x, acc[0][2]));

            uint4 tv1 = *(const uint4*)(smem + SM_T + (ebase + 8) * 832 + qp * 16);
            float2 b0v = __half22float2(*(half2*)&tv1.x);
            float2 b1v = __half22float2(*(half2*)&tv1.y);
            float2 b2v = __half22float2(*(half2*)&tv1.z);
            float2 b3v = __half22float2(*(half2*)&tv1.w);
            const float cA1 = C[nt][2], cB1 = C[nt][3];
            acc[1][0] = fmaf(cA1, b0v.x, fmaf(cB1, b2v.x, acc[1][0]));
            acc[1][1] = fmaf(cA1, b0v.y, fmaf(cB1, b2v.y, acc[1][1]));
            acc[1][2] = fmaf(cA1, b1v.x, fmaf(cB1, b3v.x, acc[1][2]));
        }
        #pragma unroll
        for (int s = 0; s < 2; s++) {
            #pragma unroll
            for (int m = 0; m < 3; m++) {
                acc[s][m] += __shfl_xor_sync(0xffffffffu, acc[s][m], 1);
                acc[s][m] += __shfl_xor_sync(0xffffffffu, acc[s][m], 2);
            }
        }

        // ng=1,2 publish partials (parity o&1); slot = (ng-1)*64 + eg*8 + r
        if (ng > 0 && c == 0) {
            float* p = ped + (o & 1) * 768 + ((ng - 1) * 64 + eg * 8 + r) * 6;
            p[0] = acc[0][0]; p[1] = acc[0][1]; p[2] = acc[0][2];
            p[3] = acc[1][0]; p[4] = acc[1][1]; p[5] = acc[1][2];
        }

        asm volatile("cp.async.wait_group 0;" ::: "memory");
        __syncthreads();

        // ng=0 combines + stores
        if (ng == 0 && c == 0) {
            const float* p1 = ped + (o & 1) * 768 + (eg * 8 + r) * 6;
            const float* p2 = p1 + 384;
            float* op0 = out + (size_t)(E0 + ebase) * (NCOUT * MO) + o * 3;
            op0[0] = acc[0][0] + p1[0] + p2[0];
            op0[1] = acc[0][1] + p1[1] + p2[1];
            op0[2] = acc[0][2] + p1[2] + p2[2];
            float* op1 = out + (size_t)(E0 + ebase + 8) * (NCOUT * MO) + o * 3;
            op1[0] = acc[1][0] + p1[3] + p2[3];
            op1[1] = acc[1][1] + p1[4] + p2[4];
            op1[2] = acc[1][2] + p1[5] + p2[5];
        }
    }
}

// ---------------- launch ----------------
extern "C" void kernel_launch(void* const* d_in, const int* in_sizes, int n_in,
                              void* d_out, int out_size) {
    const float* edges = (const float*)d_in[0];
    const float* feats = (const float*)d_in[1];
    const float* basis = (const float*)d_in[2];
    const float* W1    = (const float*)d_in[3];
    const float* b1    = (const float*)d_in[4];
    const float* g1    = (const float*)d_in[5];
    const float* be1   = (const float*)d_in[6];
    const float* W2    = (const float*)d_in[7];
    const float* b2    = (const float*)d_in[8];
    const float* g2    = (const float*)d_in[9];
    const float* be2   = (const float*)d_in[10];
    const float* W3    = (const float*)d_in[11];
    float* out = (float*)d_out;

    const int E = in_sizes[0] / EDGE_DIM;

    prep_w3<<<(MID * RADW + 255) / 256, 256>>>(W3);

    cudaFuncSetAttribute(pair_main_kernel,
                         cudaFuncAttributeMaxDynamicSharedMemorySize, SM_TOTAL);
    pair_main_kernel<<<E / 128, 768, SM_TOTAL>>>(edges, feats, basis,
                                                 W1, b1, g1, be1,
                                                 W2, b2, g2, be2, out, E);
}

// round 16
// speedup vs baseline: 1.0730x; 1.0730x over previous
#include <cuda_runtime.h>
#include <cuda_fp16.h>
#include <cstdint>

// ---------------- problem constants ----------------
#define EDGE_DIM 32
#define MID      64
#define NCIN     32
#define NCOUT    32
#define MO       3
#define QDIM     96
#define RADW     3072
#define EMAX     32768
#define NCHUNK   32
#define HP       68            // h overlay pitch (floats)

// scratch: per chunk 12288 B fragment-register-order fp16 W3 image (n-halves)
__device__ __half g_B[NCHUNK * 12288 / 2];

// ---------------- helpers ----------------
__device__ __forceinline__ float gelu_exact(float x) {
    return 0.5f * x * (1.0f + erff(x * 0.70710678118654752440f));
}
__device__ __forceinline__ float warp_allreduce_sum(float v) {
    v += __shfl_xor_sync(0xffffffffu, v, 16);
    v += __shfl_xor_sync(0xffffffffu, v, 8);
    v += __shfl_xor_sync(0xffffffffu, v, 4);
    v += __shfl_xor_sync(0xffffffffu, v, 2);
    v += __shfl_xor_sync(0xffffffffu, v, 1);
    return v;
}
__device__ __forceinline__ uint32_t pack_h2(float x, float y) {
    half2 h = __floats2half2_rn(x, y);
    return *(uint32_t*)&h;
}
__device__ __forceinline__ void mma16816(float c[4], const uint32_t a[4],
                                         uint32_t b0, uint32_t b1) {
    asm volatile(
        "mma.sync.aligned.m16n8k16.row.col.f32.f16.f16.f32 "
        "{%0,%1,%2,%3}, {%4,%5,%6,%7}, {%8,%9}, {%0,%1,%2,%3};"
        : "+f"(c[0]), "+f"(c[1]), "+f"(c[2]), "+f"(c[3])
        : "r"(a[0]), "r"(a[1]), "r"(a[2]), "r"(a[3]), "r"(b0), "r"(b1));
}
__device__ __forceinline__ void cp_async16(uint32_t smem_dst, const void* gsrc) {
    asm volatile("cp.async.cg.shared.global [%0], [%1], 16;"
                 :: "r"(smem_dst), "l"(gsrc) : "memory");
}

// ---------------- Kernel P: W3 -> fragment-register-order fp16 image ----------
// (identical layout to the 142us best: n in halves of 48)
__global__ void __launch_bounds__(256) prep_w3(const float* __restrict__ W3) {
    int idx = blockIdx.x * 256 + threadIdx.x;     // over 64*3072
    if (idx >= MID * RADW) return;
    int k = idx / RADW, n = idx % RADW;
    int chunk = n / QDIM, nl = n % QDIM;
    int ng = nl / 48, nq = nl % 48;
    int nt = nq >> 3, rr = nq & 7;
    int kt = k >> 4, kk = k & 15;
    int cc = (kk >> 1) & 3, bb = kk >> 3, hp = kk & 1;
    int lane = rr * 4 + cc;
    int j = kt * 3 + (nt >> 1);
    int r4 = ((nt & 1) << 1) + bb;
    int off = chunk * 12288 + ng * 6144 + j * 512 + lane * 16 + r4 * 4 + hp * 2;
    g_B[off >> 1] = __float2half_rn(W3[idx]);
}

// ---------------- Kernel M: fused MLP + mma.sync, 64 edges / 256 thr, 2 CTAs/SM ----
// 8 warps = 4 edge-groups x 2 n-halves; warp = 16 edges x 48 n.
#define SM_B     0                          // 2 x 12288 = 24576
#define SM_T     24576                      // 64 x 832 = 53248 -> 77824
#define SM_PED   77824                      // 2 parity x 192 floats = 1536 -> 79360
#define SM_TOTAL 79360
// prologue overlays inside T region: W (26112 B) then h (64*68*4 = 17408 B)

__global__ void __launch_bounds__(256, 2) pair_main_kernel(
    const float* __restrict__ edges,
    const float* __restrict__ feats,
    const float* __restrict__ basis,
    const float* __restrict__ W1, const float* __restrict__ b1,
    const float* __restrict__ g1, const float* __restrict__ be1,
    const float* __restrict__ W2, const float* __restrict__ b2,
    const float* __restrict__ g2, const float* __restrict__ be2,
    float* __restrict__ out,
    int E)
{
    extern __shared__ __align__(1024) char smem[];
    const uint32_t smem_u32 = (uint32_t)__cvta_generic_to_shared(smem);
    const int tid = threadIdx.x, w = tid >> 5, lane = tid & 31;
    const int r = lane >> 2, c = lane & 3;
    const int eg = w >> 1, ng = w & 1;        // eg 0..3, ng 0..1
    const long E0 = (long)blockIdx.x * 64;
    const int ebase = eg * 16 + r;            // local edge, + 8 for slot 1

    // prologue overlays (dead before T is built)
    float* Wsm = (float*)(smem + SM_T);            // 26112 B
    float* hsm = (float*)(smem + SM_T + 26112);    // 17408 B
    float* W1s = Wsm;               // 2048 floats
    float* W2s = Wsm + 2048;        // 4096 floats
    float* prm = Wsm + 6144;        // 384 floats

    const float4* gB4 = (const float4*)g_B;

    // ---- stage chunks 0,1 via cp.async (1536 lines, 6 per thread) ----
    #pragma unroll
    for (int j = 0; j < 6; j++)
        cp_async16(smem_u32 + SM_B + (tid + j * 256) * 16, gB4 + tid + j * 256);
    asm volatile("cp.async.commit_group;" ::: "memory");

    // ---- load MLP weights into overlay ----
    for (int i = tid; i < EDGE_DIM * MID; i += 256) W1s[i] = W1[i];
    for (int i = tid; i < MID * MID; i += 256)      W2s[i] = W2[i];
    if (tid < MID) {
        prm[tid] = b1[tid]; prm[MID + tid] = g1[tid]; prm[2*MID + tid] = be1[tid];
        prm[3*MID + tid] = b2[tid]; prm[4*MID + tid] = g2[tid]; prm[5*MID + tid] = be2[tid];
    }
    __syncthreads();

    // ---- fused MLP: warp w computes edges [w*8, w*8+8) ----
    for (int it = 0; it < 8; it++) {
        const int el = w * 8 + it;
        const float xv = edges[(size_t)(E0 + el) * EDGE_DIM + lane];
        float a0 = prm[lane], a1 = prm[lane + 32];
        #pragma unroll
        for (int k = 0; k < 32; k++) {
            const float xk = __shfl_sync(0xffffffffu, xv, k);
            a0 = fmaf(xk, W1s[k * MID + lane], a0);
            a1 = fmaf(xk, W1s[k * MID + lane + 32], a1);
        }
        float mean = warp_allreduce_sum(a0 + a1) * (1.0f / 64.0f);
        float d0 = a0 - mean, d1 = a1 - mean;
        float var = warp_allreduce_sum(d0 * d0 + d1 * d1) * (1.0f / 64.0f);
        float inv = rsqrtf(var + 1e-5f);
        a0 = gelu_exact(d0 * inv * prm[MID + lane]      + prm[2*MID + lane]);
        a1 = gelu_exact(d1 * inv * prm[MID + lane + 32] + prm[2*MID + lane + 32]);
        float c0 = prm[3*MID + lane], c1 = prm[3*MID + lane + 32];
        #pragma unroll
        for (int k = 0; k < 32; k++) {
            const float u  = __shfl_sync(0xffffffffu, a0, k);
            const float v2 = __shfl_sync(0xffffffffu, a1, k);
            c0 = fmaf(u,  W2s[k * MID + lane], c0);
            c0 = fmaf(v2, W2s[(k + 32) * MID + lane], c0);
            c1 = fmaf(u,  W2s[k * MID + lane + 32], c1);
            c1 = fmaf(v2, W2s[(k + 32) * MID + lane + 32], c1);
        }
        mean = warp_allreduce_sum(c0 + c1) * (1.0f / 64.0f);
        d0 = c0 - mean; d1 = c1 - mean;
        var = warp_allreduce_sum(d0 * d0 + d1 * d1) * (1.0f / 64.0f);
        inv = rsqrtf(var + 1e-5f);
        c0 = gelu_exact(d0 * inv * prm[4*MID + lane]      + prm[5*MID + lane]);
        c1 = gelu_exact(d1 * inv * prm[4*MID + lane + 32] + prm[5*MID + lane + 32]);
        hsm[el * HP + lane]      = c0;
        hsm[el * HP + lane + 32] = c1;
    }
    __syncthreads();

    // ---- A fragments from h overlay (16 edges: rows ebase, ebase+8) ----
    uint32_t A[4][4];
    {
        const float* h0 = hsm + ebase * HP;
        const float* h1 = hsm + (ebase + 8) * HP;
        #pragma unroll
        for (int kt = 0; kt < 4; kt++) {
            const int k0 = kt * 16 + 2 * c;
            float2 p0 = *(const float2*)(h0 + k0);
            float2 p1 = *(const float2*)(h0 + k0 + 8);
            float2 p2 = *(const float2*)(h1 + k0);
            float2 p3 = *(const float2*)(h1 + k0 + 8);
            A[kt][0] = pack_h2(p0.x, p0.y);
            A[kt][1] = pack_h2(p2.x, p2.y);
            A[kt][2] = pack_h2(p1.x, p1.y);
            A[kt][3] = pack_h2(p3.x, p3.y);
        }
    }
    __syncthreads();   // all h reads done; T may overwrite overlay

    // ---- T tile: [e][qp] pitch 832; one uint4 = fp16 {t0, t1} ----
    for (int idx = tid; idx < 64 * 48; idx += 256) {
        const int e = idx / 48, qp = idx - e * 48;
        const int q0 = 2 * qp, q1 = q0 + 1;
        const int i0 = q0 / 3, f0 = q0 % 3, i1 = q1 / 3, f1 = q1 % 3;
        const float* fe = feats + (size_t)(E0 + e) * (NCIN * 3);
        const float* be = basis + (size_t)(E0 + e) * 27;
        const float a0 = fe[i0*3], a1 = fe[i0*3+1], a2 = fe[i0*3+2];
        const float b0 = fe[i1*3], b1v = fe[i1*3+1], b2v = fe[i1*3+2];
        float t0[3], t1[3];
        #pragma unroll
        for (int m = 0; m < 3; m++) {
            t0[m] = a0 * be[f0*3+m] + a1  * be[9 + f0*3+m] + a2  * be[18 + f0*3+m];
            t1[m] = b0 * be[f1*3+m] + b1v * be[9 + f1*3+m] + b2v * be[18 + f1*3+m];
        }
        uint4 v;
        v.x = pack_h2(t0[0], t0[1]);
        v.y = pack_h2(t0[2], 0.0f);
        v.z = pack_h2(t1[0], t1[1]);
        v.w = pack_h2(t1[2], 0.0f);
        *(uint4*)(smem + SM_T + e * 832 + qp * 16) = v;
    }
    asm volatile("cp.async.wait_group 0;" ::: "memory");
    __syncthreads();    // T visible; B chunks 0,1 landed

    // ---- T register cache for s=0, converted to fp32 once (36 regs) ----
    float Tf[6][6];
    #pragma unroll
    for (int nt = 0; nt < 6; nt++) {
        const int qp = ng * 24 + nt * 4 + c;
        uint4 tv = *(const uint4*)(smem + SM_T + ebase * 832 + qp * 16);
        float2 u0 = __half22float2(*(half2*)&tv.x);
        float2 u1 = __half22float2(*(half2*)&tv.y);
        float2 u2 = __half22float2(*(half2*)&tv.z);
        float2 u3 = __half22float2(*(half2*)&tv.w);
        Tf[nt][0] = u0.x; Tf[nt][1] = u0.y; Tf[nt][2] = u1.x;
        Tf[nt][3] = u2.x; Tf[nt][4] = u2.y; Tf[nt][5] = u3.x;
    }

    float* ped = (float*)(smem + SM_PED);

    for (int o = 0; o < NCHUNK; o++) {
        // stage next chunk via cp.async (768 lines, 3 per thread)
        if (o + 1 < NCHUNK) {
            const uint32_t dst = smem_u32 + SM_B + ((o + 1) & 1) * 12288;
            const float4* src = gB4 + (size_t)(o + 1) * 768;
            #pragma unroll
            for (int j = 0; j < 3; j++)
                cp_async16(dst + (tid + j * 256) * 16, src + tid + j * 256);
            asm volatile("cp.async.commit_group;" ::: "memory");
        }

        const char* buf = smem + SM_B + (o & 1) * 12288 + ng * 6144;
        float C[6][4];
        #pragma unroll
        for (int nt = 0; nt < 6; nt++) {
            C[nt][0] = 0.f; C[nt][1] = 0.f; C[nt][2] = 0.f; C[nt][3] = 0.f;
        }

        #pragma unroll
        for (int kt = 0; kt < 4; kt++) {
            uint4 bh[3];
            #pragma unroll
            for (int jj = 0; jj < 3; jj++)
                bh[jj] = *(const uint4*)(buf + (kt*3 + jj) * 512 + lane * 16);
            #pragma unroll
            for (int jj = 0; jj < 3; jj++) {
                mma16816(C[2*jj],   A[kt], bh[jj].x, bh[jj].y);
                mma16816(C[2*jj+1], A[kt], bh[jj].z, bh[jj].w);
            }
        }

        // ---- epilogue: s=0 from register cache, s=1 from smem ----
        float acc[2][3];
        acc[0][0]=0.f; acc[0][1]=0.f; acc[0][2]=0.f;
        acc[1][0]=0.f; acc[1][1]=0.f; acc[1][2]=0.f;

        #pragma unroll
        for (int nt = 0; nt < 6; nt++) {
            const float cA0 = C[nt][0], cB0 = C[nt][1];
            acc[0][0] = fmaf(cA0, Tf[nt][0], fmaf(cB0, Tf[nt][3], acc[0][0]));
            acc[0][1] = fmaf(cA0, Tf[nt][1], fmaf(cB0, Tf[nt][4], acc[0][1]));
            acc[0][2] = fmaf(cA0, Tf[nt][2], fmaf(cB0, Tf[nt][5], acc[0][2]));

            const int qp = ng * 24 + nt * 4 + c;
            uint4 tv = *(const uint4*)(smem + SM_T + (ebase + 8) * 832 + qp * 16);
            float2 u0 = __half22float2(*(half2*)&tv.x);
            float2 u1 = __half22float2(*(half2*)&tv.y);
            float2 u2 = __half22float2(*(half2*)&tv.z);
            float2 u3 = __half22float2(*(half2*)&tv.w);
            const float cA1 = C[nt][2], cB1 = C[nt][3];
            acc[1][0] = fmaf(cA1, u0.x, fmaf(cB1, u2.x, acc[1][0]));
            acc[1][1] = fmaf(cA1, u0.y, fmaf(cB1, u2.y, acc[1][1]));
            acc[1][2] = fmaf(cA1, u1.x, fmaf(cB1, u3.x, acc[1][2]));
        }
        #pragma unroll
        for (int s = 0; s < 2; s++) {
            #pragma unroll
            for (int m = 0; m < 3; m++) {
                acc[s][m] += __shfl_xor_sync(0xffffffffu, acc[s][m], 1);
                acc[s][m] += __shfl_xor_sync(0xffffffffu, acc[s][m], 2);
            }
        }

        // ng=1 publishes partials (parity o&1); 16 slots (eg*8+r... eg 0..3)
        if (ng == 1 && c == 0) {
            float* p = ped + (o & 1) * 192 + (eg * 8 + r) * 6;
            p[0] = acc[0][0]; p[1] = acc[0][1]; p[2] = acc[0][2];
            p[3] = acc[1][0]; p[4] = acc[1][1]; p[5] = acc[1][2];
        }

        asm volatile("cp.async.wait_group 0;" ::: "memory");
        __syncthreads();

        // ng=0 combines + stores
        if (ng == 0 && c == 0) {
            const float* p = ped + (o & 1) * 192 + (eg * 8 + r) * 6;
            float* op0 = out + (size_t)(E0 + ebase) * (NCOUT * MO) + o * 3;
            op0[0] = acc[0][0] + p[0];
            op0[1] = acc[0][1] + p[1];
            op0[2] = acc[0][2] + p[2];
            float* op1 = out + (size_t)(E0 + ebase + 8) * (NCOUT * MO) + o * 3;
            op1[0] = acc[1][0] + p[3];
            op1[1] = acc[1][1] + p[4];
            op1[2] = acc[1][2] + p[5];
        }
    }
}

// ---------------- launch ----------------
extern "C" void kernel_launch(void* const* d_in, const int* in_sizes, int n_in,
                              void* d_out, int out_size) {
    const float* edges = (const float*)d_in[0];
    const float* feats = (const float*)d_in[1];
    const float* basis = (const float*)d_in[2];
    const float* W1    = (const float*)d_in[3];
    const float* b1    = (const float*)d_in[4];
    const float* g1    = (const float*)d_in[5];
    const float* be1   = (const float*)d_in[6];
    const float* W2    = (const float*)d_in[7];
    const float* b2    = (const float*)d_in[8];
    const float* g2    = (const float*)d_in[9];
    const float* be2   = (const float*)d_in[10];
    const float* W3    = (const float*)d_in[11];
    float* out = (float*)d_out;

    const int E = in_sizes[0] / EDGE_DIM;

    prep_w3<<<(MID * RADW + 255) / 256, 256>>>(W3);

    cudaFuncSetAttribute(pair_main_kernel,
                         cudaFuncAttributeMaxDynamicSharedMemorySize, SM_TOTAL);
    pair_main_kernel<<<E / 64, 256, SM_TOTAL>>>(edges, feats, basis,
                                                W1, b1, g1, be1,
                                                W2, b2, g2, be2, out, E);
}

// round 17
// speedup vs baseline: 1.0732x; 1.0002x over previous
#include <cuda_runtime.h>
#include <cuda_fp16.h>
#include <cstdint>

// ---------------- problem constants ----------------
#define EDGE_DIM 32
#define MID      64
#define NCIN     32
#define NCOUT    32
#define MO       3
#define QDIM     96
#define RADW     3072
#define EMAX     32768
#define NCHUNK   32
#define HP       68            // h overlay pitch (floats)

// scratch: per chunk 12288 B fragment-register-order fp16 W3 image (n-halves)
__device__ __half g_B[NCHUNK * 12288 / 2];

// ---------------- helpers ----------------
__device__ __forceinline__ float gelu_exact(float x) {
    return 0.5f * x * (1.0f + erff(x * 0.70710678118654752440f));
}
__device__ __forceinline__ float warp_allreduce_sum(float v) {
    v += __shfl_xor_sync(0xffffffffu, v, 16);
    v += __shfl_xor_sync(0xffffffffu, v, 8);
    v += __shfl_xor_sync(0xffffffffu, v, 4);
    v += __shfl_xor_sync(0xffffffffu, v, 2);
    v += __shfl_xor_sync(0xffffffffu, v, 1);
    return v;
}
__device__ __forceinline__ uint32_t pack_h2(float x, float y) {
    half2 h = __floats2half2_rn(x, y);
    return *(uint32_t*)&h;
}
__device__ __forceinline__ void mma16816(float c[4], const uint32_t a[4],
                                         uint32_t b0, uint32_t b1) {
    asm volatile(
        "mma.sync.aligned.m16n8k16.row.col.f32.f16.f16.f32 "
        "{%0,%1,%2,%3}, {%4,%5,%6,%7}, {%8,%9}, {%0,%1,%2,%3};"
        : "+f"(c[0]), "+f"(c[1]), "+f"(c[2]), "+f"(c[3])
        : "r"(a[0]), "r"(a[1]), "r"(a[2]), "r"(a[3]), "r"(b0), "r"(b1));
}
__device__ __forceinline__ void cp_async16(uint32_t smem_dst, const void* gsrc) {
    asm volatile("cp.async.cg.shared.global [%0], [%1], 16;"
                 :: "r"(smem_dst), "l"(gsrc) : "memory");
}

// ---------------- Kernel P: W3 -> fragment-register-order fp16 image ----------
__global__ void __launch_bounds__(256) prep_w3(const float* __restrict__ W3) {
    int idx = blockIdx.x * 256 + threadIdx.x;     // over 64*3072
    if (idx >= MID * RADW) return;
    int k = idx / RADW, n = idx % RADW;
    int chunk = n / QDIM, nl = n % QDIM;
    int ng = nl / 48, nq = nl % 48;
    int nt = nq >> 3, rr = nq & 7;
    int kt = k >> 4, kk = k & 15;
    int cc = (kk >> 1) & 3, bb = kk >> 3, hp = kk & 1;
    int lane = rr * 4 + cc;
    int j = kt * 3 + (nt >> 1);
    int r4 = ((nt & 1) << 1) + bb;
    int off = chunk * 12288 + ng * 6144 + j * 512 + lane * 16 + r4 * 4 + hp * 2;
    g_B[off >> 1] = __float2half_rn(W3[idx]);
}

// ---------------- Kernel M: 64 edges / 256 thr, 2 CTAs/SM, paired chunks ----
// 8 warps = 4 edge-groups x 2 n-halves; warp = 16 edges x 48 n.
// B ring: 4 x 12288; one sync per 2 chunks.
#define SM_B     0                          // 4 x 12288 = 49152
#define SM_T     49152                      // 64 x 832 = 53248 -> 102400
#define SM_PED   102400                     // 2 parity x 384 floats = 3072 -> 105472
#define SM_TOTAL 105472
// prologue overlays inside T region: W (26112 B) then h (64*68*4 = 17408 B)

__global__ void __launch_bounds__(256, 2) pair_main_kernel(
    const float* __restrict__ edges,
    const float* __restrict__ feats,
    const float* __restrict__ basis,
    const float* __restrict__ W1, const float* __restrict__ b1,
    const float* __restrict__ g1, const float* __restrict__ be1,
    const float* __restrict__ W2, const float* __restrict__ b2,
    const float* __restrict__ g2, const float* __restrict__ be2,
    float* __restrict__ out,
    int E)
{
    extern __shared__ __align__(1024) char smem[];
    const uint32_t smem_u32 = (uint32_t)__cvta_generic_to_shared(smem);
    const int tid = threadIdx.x, w = tid >> 5, lane = tid & 31;
    const int r = lane >> 2, c = lane & 3;
    const int eg = w >> 1, ng = w & 1;        // eg 0..3, ng 0..1
    const long E0 = (long)blockIdx.x * 64;
    const int ebase = eg * 16 + r;            // local edge, + 8 for slot 1

    // prologue overlays (dead before T is built)
    float* Wsm = (float*)(smem + SM_T);            // 26112 B
    float* hsm = (float*)(smem + SM_T + 26112);    // 17408 B
    float* W1s = Wsm;               // 2048 floats
    float* W2s = Wsm + 2048;        // 4096 floats
    float* prm = Wsm + 6144;        // 384 floats

    const float4* gB4 = (const float4*)g_B;

    // ---- stage chunks 0,1 via cp.async (1536 lines, 6 per thread) ----
    #pragma unroll
    for (int j = 0; j < 6; j++)
        cp_async16(smem_u32 + SM_B + (tid + j * 256) * 16, gB4 + tid + j * 256);
    asm volatile("cp.async.commit_group;" ::: "memory");

    // ---- load MLP weights into overlay ----
    for (int i = tid; i < EDGE_DIM * MID; i += 256) W1s[i] = W1[i];
    for (int i = tid; i < MID * MID; i += 256)      W2s[i] = W2[i];
    if (tid < MID) {
        prm[tid] = b1[tid]; prm[MID + tid] = g1[tid]; prm[2*MID + tid] = be1[tid];
        prm[3*MID + tid] = b2[tid]; prm[4*MID + tid] = g2[tid]; prm[5*MID + tid] = be2[tid];
    }
    __syncthreads();

    // ---- fused MLP: warp w computes edges [w*8, w*8+8) ----
    for (int it = 0; it < 8; it++) {
        const int el = w * 8 + it;
        const float xv = edges[(size_t)(E0 + el) * EDGE_DIM + lane];
        float a0 = prm[lane], a1 = prm[lane + 32];
        #pragma unroll
        for (int k = 0; k < 32; k++) {
            const float xk = __shfl_sync(0xffffffffu, xv, k);
            a0 = fmaf(xk, W1s[k * MID + lane], a0);
            a1 = fmaf(xk, W1s[k * MID + lane + 32], a1);
        }
        float mean = warp_allreduce_sum(a0 + a1) * (1.0f / 64.0f);
        float d0 = a0 - mean, d1 = a1 - mean;
        float var = warp_allreduce_sum(d0 * d0 + d1 * d1) * (1.0f / 64.0f);
        float inv = rsqrtf(var + 1e-5f);
        a0 = gelu_exact(d0 * inv * prm[MID + lane]      + prm[2*MID + lane]);
        a1 = gelu_exact(d1 * inv * prm[MID + lane + 32] + prm[2*MID + lane + 32]);
        float c0 = prm[3*MID + lane], c1 = prm[3*MID + lane + 32];
        #pragma unroll
        for (int k = 0; k < 32; k++) {
            const float u  = __shfl_sync(0xffffffffu, a0, k);
            const float v2 = __shfl_sync(0xffffffffu, a1, k);
            c0 = fmaf(u,  W2s[k * MID + lane], c0);
            c0 = fmaf(v2, W2s[(k + 32) * MID + lane], c0);
            c1 = fmaf(u,  W2s[k * MID + lane + 32], c1);
            c1 = fmaf(v2, W2s[(k + 32) * MID + lane + 32], c1);
        }
        mean = warp_allreduce_sum(c0 + c1) * (1.0f / 64.0f);
        d0 = c0 - mean; d1 = c1 - mean;
        var = warp_allreduce_sum(d0 * d0 + d1 * d1) * (1.0f / 64.0f);
        inv = rsqrtf(var + 1e-5f);
        c0 = gelu_exact(d0 * inv * prm[4*MID + lane]      + prm[5*MID + lane]);
        c1 = gelu_exact(d1 * inv * prm[4*MID + lane + 32] + prm[5*MID + lane + 32]);
        hsm[el * HP + lane]      = c0;
        hsm[el * HP + lane + 32] = c1;
    }
    __syncthreads();

    // ---- A fragments from h overlay (16 edges: rows ebase, ebase+8) ----
    uint32_t A[4][4];
    {
        const float* h0 = hsm + ebase * HP;
        const float* h1 = hsm + (ebase + 8) * HP;
        #pragma unroll
        for (int kt = 0; kt < 4; kt++) {
            const int k0 = kt * 16 + 2 * c;
            float2 p0 = *(const float2*)(h0 + k0);
            float2 p1 = *(const float2*)(h0 + k0 + 8);
            float2 p2 = *(const float2*)(h1 + k0);
            float2 p3 = *(const float2*)(h1 + k0 + 8);
            A[kt][0] = pack_h2(p0.x, p0.y);
            A[kt][1] = pack_h2(p2.x, p2.y);
            A[kt][2] = pack_h2(p1.x, p1.y);
            A[kt][3] = pack_h2(p3.x, p3.y);
        }
    }
    __syncthreads();   // all h reads done; T may overwrite overlay

    // ---- T tile: [e][qp] pitch 832; one uint4 = fp16 {t0, t1} ----
    for (int idx = tid; idx < 64 * 48; idx += 256) {
        const int e = idx / 48, qp = idx - e * 48;
        const int q0 = 2 * qp, q1 = q0 + 1;
        const int i0 = q0 / 3, f0 = q0 % 3, i1 = q1 / 3, f1 = q1 % 3;
        const float* fe = feats + (size_t)(E0 + e) * (NCIN * 3);
        const float* be = basis + (size_t)(E0 + e) * 27;
        const float a0 = fe[i0*3], a1 = fe[i0*3+1], a2 = fe[i0*3+2];
        const float b0 = fe[i1*3], b1v = fe[i1*3+1], b2v = fe[i1*3+2];
        float t0[3], t1[3];
        #pragma unroll
        for (int m = 0; m < 3; m++) {
            t0[m] = a0 * be[f0*3+m] + a1  * be[9 + f0*3+m] + a2  * be[18 + f0*3+m];
            t1[m] = b0 * be[f1*3+m] + b1v * be[9 + f1*3+m] + b2v * be[18 + f1*3+m];
        }
        uint4 v;
        v.x = pack_h2(t0[0], t0[1]);
        v.y = pack_h2(t0[2], 0.0f);
        v.z = pack_h2(t1[0], t1[1]);
        v.w = pack_h2(t1[2], 0.0f);
        *(uint4*)(smem + SM_T + e * 832 + qp * 16) = v;
    }
    asm volatile("cp.async.wait_group 0;" ::: "memory");
    __syncthreads();    // T visible; B chunks 0,1 landed

    // ---- T register cache for s=0, converted to fp32 once (36 regs) ----
    float Tf[6][6];
    #pragma unroll
    for (int nt = 0; nt < 6; nt++) {
        const int qp = ng * 24 + nt * 4 + c;
        uint4 tv = *(const uint4*)(smem + SM_T + ebase * 832 + qp * 16);
        float2 u0 = __half22float2(*(half2*)&tv.x);
        float2 u1 = __half22float2(*(half2*)&tv.y);
        float2 u2 = __half22float2(*(half2*)&tv.z);
        float2 u3 = __half22float2(*(half2*)&tv.w);
        Tf[nt][0] = u0.x; Tf[nt][1] = u0.y; Tf[nt][2] = u1.x;
        Tf[nt][3] = u2.x; Tf[nt][4] = u2.y; Tf[nt][5] = u3.x;
    }

    float* ped = (float*)(smem + SM_PED);

    for (int o = 0; o < NCHUNK; o += 2) {
        // stage next pair into the other two ring slots (6 lines per thread)
        if (o + 2 < NCHUNK) {
            #pragma unroll
            for (int j = 0; j < 6; j++) {
                const int idx = tid + j * 256;          // 0..1535
                const int ch = idx / 768, off = idx - ch * 768;
                const int gch = o + 2 + ch;
                cp_async16(smem_u32 + SM_B + (gch & 3) * 12288 + off * 16,
                           gB4 + (size_t)gch * 768 + off);
            }
            asm volatile("cp.async.commit_group;" ::: "memory");
        }

        float accP[2][2][3];    // [chunk-in-pair][s][m]
        #pragma unroll
        for (int h = 0; h < 2; h++) {
            const char* buf = smem + SM_B + ((o + h) & 3) * 12288 + ng * 6144;
            float C[6][4];
            #pragma unroll
            for (int nt = 0; nt < 6; nt++) {
                C[nt][0] = 0.f; C[nt][1] = 0.f; C[nt][2] = 0.f; C[nt][3] = 0.f;
            }
            #pragma unroll
            for (int kt = 0; kt < 4; kt++) {
                uint4 bh[3];
                #pragma unroll
                for (int jj = 0; jj < 3; jj++)
                    bh[jj] = *(const uint4*)(buf + (kt*3 + jj) * 512 + lane * 16);
                #pragma unroll
                for (int jj = 0; jj < 3; jj++) {
                    mma16816(C[2*jj],   A[kt], bh[jj].x, bh[jj].y);
                    mma16816(C[2*jj+1], A[kt], bh[jj].z, bh[jj].w);
                }
            }

            float (*acc)[3] = accP[h];
            acc[0][0]=0.f; acc[0][1]=0.f; acc[0][2]=0.f;
            acc[1][0]=0.f; acc[1][1]=0.f; acc[1][2]=0.f;
            #pragma unroll
            for (int nt = 0; nt < 6; nt++) {
                const float cA0 = C[nt][0], cB0 = C[nt][1];
                acc[0][0] = fmaf(cA0, Tf[nt][0], fmaf(cB0, Tf[nt][3], acc[0][0]));
                acc[0][1] = fmaf(cA0, Tf[nt][1], fmaf(cB0, Tf[nt][4], acc[0][1]));
                acc[0][2] = fmaf(cA0, Tf[nt][2], fmaf(cB0, Tf[nt][5], acc[0][2]));

                const int qp = ng * 24 + nt * 4 + c;
                uint4 tv = *(const uint4*)(smem + SM_T + (ebase + 8) * 832 + qp * 16);
                float2 u0 = __half22float2(*(half2*)&tv.x);
                float2 u1 = __half22float2(*(half2*)&tv.y);
                float2 u2 = __half22float2(*(half2*)&tv.z);
                float2 u3 = __half22float2(*(half2*)&tv.w);
                const float cA1 = C[nt][2], cB1 = C[nt][3];
                acc[1][0] = fmaf(cA1, u0.x, fmaf(cB1, u2.x, acc[1][0]));
                acc[1][1] = fmaf(cA1, u0.y, fmaf(cB1, u2.y, acc[1][1]));
                acc[1][2] = fmaf(cA1, u1.x, fmaf(cB1, u3.x, acc[1][2]));
            }
            #pragma unroll
            for (int s = 0; s < 2; s++) {
                #pragma unroll
                for (int m = 0; m < 3; m++) {
                    acc[s][m] += __shfl_xor_sync(0xffffffffu, acc[s][m], 1);
                    acc[s][m] += __shfl_xor_sync(0xffffffffu, acc[s][m], 2);
                }
            }
            // ng=1 publishes both chunks' partials (parity (o>>1)&1)
            if (ng == 1 && c == 0) {
                float* p = ped + ((o >> 1) & 1) * 384 + (eg * 8 + r) * 12 + h * 6;
                p[0] = acc[0][0]; p[1] = acc[0][1]; p[2] = acc[0][2];
                p[3] = acc[1][0]; p[4] = acc[1][1]; p[5] = acc[1][2];
            }
        }

        asm volatile("cp.async.wait_group 0;" ::: "memory");
        __syncthreads();

        // ng=0 combines + stores both chunks
        if (ng == 0 && c == 0) {
            const float* pb = ped + ((o >> 1) & 1) * 384 + (eg * 8 + r) * 12;
            #pragma unroll
            for (int h = 0; h < 2; h++) {
                const float* p = pb + h * 6;
                float* op0 = out + (size_t)(E0 + ebase) * (NCOUT * MO) + (o + h) * 3;
                op0[0] = accP[h][0][0] + p[0];
                op0[1] = accP[h][0][1] + p[1];
                op0[2] = accP[h][0][2] + p[2];
                float* op1 = out + (size_t)(E0 + ebase + 8) * (NCOUT * MO) + (o + h) * 3;
                op1[0] = accP[h][1][0] + p[3];
                op1[1] = accP[h][1][1] + p[4];
                op1[2] = accP[h][1][2] + p[5];
            }
        }
    }
}

// ---------------- launch ----------------
extern "C" void kernel_launch(void* const* d_in, const int* in_sizes, int n_in,
                              void* d_out, int out_size) {
    const float* edges = (const float*)d_in[0];
    const float* feats = (const float*)d_in[1];
    const float* basis = (const float*)d_in[2];
    const float* W1    = (const float*)d_in[3];
    const float* b1    = (const float*)d_in[4];
    const float* g1    = (const float*)d_in[5];
    const float* be1   = (const float*)d_in[6];
    const float* W2    = (const float*)d_in[7];
    const float* b2    = (const float*)d_in[8];
    const float* g2    = (const float*)d_in[9];
    const float* be2   = (const float*)d_in[10];
    const float* W3    = (const float*)d_in[11];
    float* out = (float*)d_out;

    const int E = in_sizes[0] / EDGE_DIM;

    prep_w3<<<(MID * RADW + 255) / 256, 256>>>(W3);

    cudaFuncSetAttribute(pair_main_kernel,
                         cudaFuncAttributeMaxDynamicSharedMemorySize, SM_TOTAL);
    pair_main_kernel<<<E / 64, 256, SM_TOTAL>>>(edges, feats, basis,
                                                W1, b1, g1, be1,
                                                W2, b2, g2, be2, out, E);
}